// round 12
// baseline (speedup 1.0000x reference)
#include <cuda_runtime.h>
#include <cuda_fp16.h>
#include <math.h>
#include <stdint.h>

#define CHUNKT   128
#define BM       128
#define BN       128
#define BK       32      // K elems per stage
#define KSTR     40      // smem row stride in halves (80B): LDS.32 conflict-free
#define AMATB    (128 * KSTR * 2)          // 10240 B per matrix per stage
#define STAGEB   (2 * AMATB)               // 20480 B (A + B)
#define NSTAGE   3

// Scratch (__device__ globals: no allocation allowed)
__device__ __half g_WT[1024 * 1024];             // W^T fp16, [H][D] K-major
__device__ __half g_A16[8 * 16 * 128 * 1024];    // gathered A fp16, [b][slot][row][k]

// ---------------------------------------------------------------------------
// helpers
// ---------------------------------------------------------------------------
__device__ __forceinline__ uint32_t cvta_shared(const void* p) {
    uint32_t a;
    asm("{ .reg .u64 t; cvta.to.shared.u64 t, %1; cvt.u32.u64 %0, t; }" : "=r"(a) : "l"(p));
    return a;
}
__device__ __forceinline__ void cp_async16(uint32_t dst, const void* src) {
    asm volatile("cp.async.cg.shared.global [%0], [%1], 16;" :: "r"(dst), "l"(src));
}
__device__ __forceinline__ uint32_t f2h2(float lo, float hi) {
    uint32_t r;
    asm("cvt.rn.f16x2.f32 %0, %1, %2;" : "=r"(r) : "f"(hi), "f"(lo));
    return r;
}
__device__ __forceinline__ void mma_f16(float c[4], uint32_t a0, uint32_t a1,
                                        uint32_t a2, uint32_t a3,
                                        uint32_t b0, uint32_t b1) {
    asm volatile(
        "mma.sync.aligned.m16n8k16.row.col.f32.f16.f16.f32 "
        "{%0,%1,%2,%3}, {%4,%5,%6,%7}, {%8,%9}, {%0,%1,%2,%3};"
        : "+f"(c[0]), "+f"(c[1]), "+f"(c[2]), "+f"(c[3])
        : "r"(a0), "r"(a1), "r"(a2), "r"(a3), "r"(b0), "r"(b1));
}

// selection mask -> (nsel, chunk of slot)
__device__ __forceinline__ unsigned long long sel_mask(const int* __restrict__ ci,
                                                       int b, int sample) {
    unsigned long long m = 0ull;
    #pragma unroll
    for (int i = 0; i < 16; ++i) m |= (1ull << ci[b * sample + i]);
    return m;
}
__device__ __forceinline__ int nth_set_bit(unsigned long long m, int n) {
    int c = 0;
    for (;; ++c) {
        if ((m >> c) & 1ull) { if (n == 0) break; --n; }
    }
    return c;
}

// ---------------------------------------------------------------------------
// Kernel 1: W[D,H] -> g_WT[H,D], fp32 -> fp16(rn) fused.
// ---------------------------------------------------------------------------
__global__ void transpose_kernel(const float* __restrict__ W, int D, int H) {
    __shared__ float tile[32][33];
    int h0 = blockIdx.x * 32, d0 = blockIdx.y * 32;
    int tx = threadIdx.x, ty = threadIdx.y;   // 32 x 8
    #pragma unroll
    for (int i = 0; i < 32; i += 8)
        tile[ty + i][tx] = W[(size_t)(d0 + ty + i) * H + h0 + tx];
    __syncthreads();
    #pragma unroll
    for (int i = 0; i < 32; i += 8)
        g_WT[(size_t)(h0 + ty + i) * D + d0 + tx] = __float2half_rn(tile[tx][ty + i]);
}

// ---------------------------------------------------------------------------
// Kernel 2: gather selected chunks of data, fp32 -> fp16, into g_A16.
// One CTA per (slot, b); dead slots skip (GEMM zero-fills independently).
// ---------------------------------------------------------------------------
__global__ void __launch_bounds__(256)
convert_a_kernel(const float* __restrict__ data,
                 const int* __restrict__ chunk_idx,
                 int D, int T, int sample) {
    const int slot = blockIdx.x;
    const int b    = blockIdx.y;
    const unsigned long long m = sel_mask(chunk_idx, b, sample);
    if (slot >= __popcll(m)) return;
    const int chunk = nth_set_bit(m, slot);

    const float4* src = reinterpret_cast<const float4*>(
        data + (size_t)b * T * D + (size_t)chunk * CHUNKT * D);
    uint2* dst = reinterpret_cast<uint2*>(
        g_A16 + ((size_t)(b * sample + slot) * CHUNKT) * D);

    const int total = CHUNKT * D / 4;        // 32768 float4
    for (int i = threadIdx.x; i < total; i += 256) {
        float4 v = src[i];
        dst[i] = make_uint2(f2h2(v.x, v.y), f2h2(v.z, v.w));
    }
}

// ---------------------------------------------------------------------------
// Kernel 3: fp16 mma.sync GEMM (f32 accum). One CTA = 128(M)x128(N), K = D.
// A and B both fp16 in smem via cp.async 3-stage pipeline; every fragment is
// one LDS.32, zero cvt in the hot loop. 8 warps (2m x 4n), warp tile 64x32.
// Epilogue fuses (+bias +PE(t,h)) * sqrt(128). Dead slots zero-fill.
// ---------------------------------------------------------------------------
__global__ void __launch_bounds__(256, 2)
chunk_gemm_mma(const float* __restrict__ bias,
               const int* __restrict__ chunk_idx,
               float* __restrict__ out,
               int D, int H, int sample) {
    extern __shared__ __align__(16) char smem[];
    __shared__ float s_div[BN / 2];
    __shared__ float s_bias[BN];

    const int ntile = blockIdx.x;
    const int slot  = blockIdx.y;
    const int b     = blockIdx.z;
    const int n0    = ntile * BN;
    const int Smax  = sample * CHUNKT;
    const int tid   = threadIdx.x;
    const int wid   = tid >> 5;
    const int lane  = tid & 31;

    float* outp = out + ((size_t)b * Smax + (size_t)slot * CHUNKT) * H + n0;

    const unsigned long long m = sel_mask(chunk_idx, b, sample);
    const int nsel = __popcll(m);

    if (slot >= nsel) {                      // zero-fill 128 x 128 tile
        float4 z = make_float4(0.f, 0.f, 0.f, 0.f);
        #pragma unroll
        for (int i = 0; i < 16; ++i) {
            int idx = i * 256 + tid;
            int r = idx >> 5, c4 = (idx & 31) * 4;
            *reinterpret_cast<float4*>(outp + (size_t)r * H + c4) = z;
        }
        return;
    }
    const int chunk = nth_set_bit(m, slot);  // needed for PE time index

    const __half* Agm = g_A16 + ((size_t)(b * sample + slot) * CHUNKT) * D;
    const __half* Bgm = g_WT + (size_t)n0 * D;

    if (tid < BN / 2)
        s_div[tid] = __expf((float)(2 * ((n0 >> 1) + tid)) * (-9.210340371976184f / (float)H));
    if (tid < BN) s_bias[tid] = bias[n0 + tid];

    const uint32_t sbase = cvta_shared(smem);

    // cp.async map: per stage each matrix = 128 rows x 32 halves (4 x 16B/row).
    // 512 copies per matrix, 2 per thread. idx = i*256+tid; r=idx>>2, kp=idx&3.
    auto load_stage = [&](int kc, int st) {
        const int k0 = kc * BK;
        const uint32_t abase = sbase + st * STAGEB;
        const uint32_t bbase = abase + AMATB;
        #pragma unroll
        for (int i = 0; i < 2; ++i) {
            int idx = i * 256 + tid;
            int r = idx >> 2, kp = idx & 3;
            cp_async16(abase + r * (KSTR * 2) + kp * 16,
                       Agm + (size_t)r * D + k0 + kp * 8);
        }
        #pragma unroll
        for (int i = 0; i < 2; ++i) {
            int idx = i * 256 + tid;
            int r = idx >> 2, kp = idx & 3;
            cp_async16(bbase + r * (KSTR * 2) + kp * 16,
                       Bgm + (size_t)r * D + k0 + kp * 8);
        }
        asm volatile("cp.async.commit_group;" ::: "memory");
    };

    // Warp tiling: wm in {0,1} (64 rows), wn in {0..3} (32 cols)
    const int wm = wid & 1;
    const int wn = wid >> 1;

    float acc[4][4][4];
    #pragma unroll
    for (int mt = 0; mt < 4; ++mt)
        #pragma unroll
        for (int nt = 0; nt < 4; ++nt)
            #pragma unroll
            for (int q = 0; q < 4; ++q) acc[mt][nt][q] = 0.f;

    const int NCH = D / BK;                  // 32
    load_stage(0, 0);
    load_stage(1, 1);

    for (int c = 0; c < NCH; ++c) {
        asm volatile("cp.async.wait_group 1;" ::: "memory");
        __syncthreads();
        if (c + 2 < NCH) load_stage(c + 2, (c + 2) % NSTAGE);
        else             asm volatile("cp.async.commit_group;" ::: "memory");

        const __half* As = reinterpret_cast<const __half*>(smem + (c % NSTAGE) * STAGEB);
        const __half* Bs = reinterpret_cast<const __half*>(smem + (c % NSTAGE) * STAGEB + AMATB);

        #pragma unroll
        for (int k16 = 0; k16 < 2; ++k16) {
            const int kb = k16 * 16 + (lane & 3) * 2;    // even half index
            uint32_t af[4][4], bf[4][2];
            #pragma unroll
            for (int mt = 0; mt < 4; ++mt) {
                const int mr = wm * 64 + mt * 16 + (lane >> 2);
                af[mt][0] = *reinterpret_cast<const uint32_t*>(&As[(mr)     * KSTR + kb]);
                af[mt][1] = *reinterpret_cast<const uint32_t*>(&As[(mr + 8) * KSTR + kb]);
                af[mt][2] = *reinterpret_cast<const uint32_t*>(&As[(mr)     * KSTR + kb + 8]);
                af[mt][3] = *reinterpret_cast<const uint32_t*>(&As[(mr + 8) * KSTR + kb + 8]);
            }
            #pragma unroll
            for (int nt = 0; nt < 4; ++nt) {
                const int nr = wn * 32 + nt * 8 + (lane >> 2);
                bf[nt][0] = *reinterpret_cast<const uint32_t*>(&Bs[nr * KSTR + kb]);
                bf[nt][1] = *reinterpret_cast<const uint32_t*>(&Bs[nr * KSTR + kb + 8]);
            }
            #pragma unroll
            for (int mt = 0; mt < 4; ++mt)
                #pragma unroll
                for (int nt = 0; nt < 4; ++nt)
                    mma_f16(acc[mt][nt], af[mt][0], af[mt][1], af[mt][2], af[mt][3],
                            bf[nt][0], bf[nt][1]);
        }
    }

    // Epilogue: (acc + bias + PE(t,h)) * sqrt(128)
    const float scale = 11.313708498984761f;   // sqrt(128)
    const int   qrow  = lane >> 2;             // 0..7
    const int   qcol  = (lane & 3) * 2;        // 0,2,4,6

    #pragma unroll
    for (int mt = 0; mt < 4; ++mt) {
        #pragma unroll
        for (int nt = 0; nt < 4; ++nt) {
            const int col = wn * 32 + nt * 8 + qcol;     // even local col
            const float bs0 = s_bias[col], bs1 = s_bias[col + 1];
            const float dv  = s_div[col >> 1];
            #pragma unroll
            for (int h = 0; h < 2; ++h) {                // row halves (+0, +8)
                const int row = wm * 64 + mt * 16 + h * 8 + qrow;
                float s, cc;
                __sincosf((float)(chunk * CHUNKT + row) * dv, &s, &cc);
                float2 v;
                v.x = (acc[mt][nt][h * 2 + 0] + bs0 + s)  * scale;
                v.y = (acc[mt][nt][h * 2 + 1] + bs1 + cc) * scale;
                *reinterpret_cast<float2*>(outp + (size_t)row * H + col) = v;
            }
        }
    }
}

// ---------------------------------------------------------------------------
// Launcher. Inputs: state, data, W, b, chunk_idx. Output float32.
// ---------------------------------------------------------------------------
extern "C" void kernel_launch(void* const* d_in, const int* in_sizes, int n_in,
                              void* d_out, int out_size) {
    const float* data      = (const float*)d_in[1];
    const float* W         = (const float*)d_in[2];
    const float* bias      = (const float*)d_in[3];
    const int*   chunk_idx = (const int*)d_in[4];
    float*       out       = (float*)d_out;

    const int H = in_sizes[3];                // 1024
    const int D = in_sizes[2] / H;            // 1024
    const int B = in_sizes[0] / (64 * H);     // 8
    const int T = in_sizes[1] / (B * D);      // 8192
    const int sample = in_sizes[4] / B;       // 16

    transpose_kernel<<<dim3(H / 32, D / 32), dim3(32, 8)>>>(W, D, H);
    convert_a_kernel<<<dim3(sample, B), 256>>>(data, chunk_idx, D, T, sample);

    const int SMEM_BYTES = NSTAGE * STAGEB;   // 61440
    cudaFuncSetAttribute(chunk_gemm_mma,
                         cudaFuncAttributeMaxDynamicSharedMemorySize, SMEM_BYTES);
    dim3 grid(H / BN, sample, B);
    chunk_gemm_mma<<<grid, 256, SMEM_BYTES>>>(bias, chunk_idx, out, D, H, sample);
}

// round 13
// speedup vs baseline: 1.2105x; 1.2105x over previous
#include <cuda_runtime.h>
#include <cuda_fp16.h>
#include <math.h>
#include <stdint.h>

#define CHUNKT   128
#define BM       128
#define BN       128
#define BK       32      // K elems per stage
#define KSTR     40      // smem row stride in halves (80B): LDSM conflict-free
#define AMATB    (128 * KSTR * 2)          // 10240 B per matrix per stage
#define STAGEB   (2 * AMATB)               // 20480 B (A + B)
#define NSTAGE   3

// Scratch (__device__ globals: no allocation allowed)
__device__ __half g_WT[1024 * 1024];             // W^T fp16, [H][D] K-major
__device__ __half g_A16[8 * 16 * 128 * 1024];    // gathered A fp16, [b][slot][row][k]

// ---------------------------------------------------------------------------
// helpers
// ---------------------------------------------------------------------------
__device__ __forceinline__ uint32_t cvta_shared(const void* p) {
    uint32_t a;
    asm("{ .reg .u64 t; cvta.to.shared.u64 t, %1; cvt.u32.u64 %0, t; }" : "=r"(a) : "l"(p));
    return a;
}
__device__ __forceinline__ void cp_async16(uint32_t dst, const void* src) {
    asm volatile("cp.async.cg.shared.global [%0], [%1], 16;" :: "r"(dst), "l"(src));
}
__device__ __forceinline__ uint32_t f2h2(float lo, float hi) {
    uint32_t r;
    asm("cvt.rn.f16x2.f32 %0, %1, %2;" : "=r"(r) : "f"(hi), "f"(lo));
    return r;
}
__device__ __forceinline__ void ldsm4(uint32_t& r0, uint32_t& r1, uint32_t& r2,
                                      uint32_t& r3, uint32_t addr) {
    asm volatile("ldmatrix.sync.aligned.m8n8.x4.shared.b16 {%0,%1,%2,%3}, [%4];"
                 : "=r"(r0), "=r"(r1), "=r"(r2), "=r"(r3) : "r"(addr));
}
__device__ __forceinline__ void mma_f16(float c[4], uint32_t a0, uint32_t a1,
                                        uint32_t a2, uint32_t a3,
                                        uint32_t b0, uint32_t b1) {
    asm volatile(
        "mma.sync.aligned.m16n8k16.row.col.f32.f16.f16.f32 "
        "{%0,%1,%2,%3}, {%4,%5,%6,%7}, {%8,%9}, {%0,%1,%2,%3};"
        : "+f"(c[0]), "+f"(c[1]), "+f"(c[2]), "+f"(c[3])
        : "r"(a0), "r"(a1), "r"(a2), "r"(a3), "r"(b0), "r"(b1));
}

__device__ __forceinline__ unsigned long long sel_mask(const int* __restrict__ ci,
                                                       int b, int sample) {
    unsigned long long m = 0ull;
    #pragma unroll
    for (int i = 0; i < 16; ++i) m |= (1ull << ci[b * sample + i]);
    return m;
}
__device__ __forceinline__ int nth_set_bit(unsigned long long m, int n) {
    int c = 0;
    for (;; ++c) {
        if ((m >> c) & 1ull) { if (n == 0) break; --n; }
    }
    return c;
}

// ---------------------------------------------------------------------------
// Kernel 1: W[D,H] -> g_WT[H,D], fp32 -> fp16(rn) fused.
// ---------------------------------------------------------------------------
__global__ void transpose_kernel(const float* __restrict__ W, int D, int H) {
    __shared__ float tile[32][33];
    int h0 = blockIdx.x * 32, d0 = blockIdx.y * 32;
    int tx = threadIdx.x, ty = threadIdx.y;   // 32 x 8
    #pragma unroll
    for (int i = 0; i < 32; i += 8)
        tile[ty + i][tx] = W[(size_t)(d0 + ty + i) * H + h0 + tx];
    __syncthreads();
    #pragma unroll
    for (int i = 0; i < 32; i += 8)
        g_WT[(size_t)(h0 + ty + i) * D + d0 + tx] = __float2half_rn(tile[tx][ty + i]);
}

// ---------------------------------------------------------------------------
// Kernel 2: gather selected chunks, fp32 -> fp16, into g_A16.
// Grid (sample, B, 8): 1024 CTAs, each converts a 16KB slab (16 f4/thread).
// ---------------------------------------------------------------------------
__global__ void __launch_bounds__(256)
convert_a_kernel(const float* __restrict__ data,
                 const int* __restrict__ chunk_idx,
                 int D, int T, int sample) {
    const int slot = blockIdx.x;
    const int b    = blockIdx.y;
    const unsigned long long m = sel_mask(chunk_idx, b, sample);
    if (slot >= __popcll(m)) return;
    const int chunk = nth_set_bit(m, slot);

    const float4* src = reinterpret_cast<const float4*>(
        data + (size_t)b * T * D + (size_t)chunk * CHUNKT * D);
    uint2* dst = reinterpret_cast<uint2*>(
        g_A16 + ((size_t)(b * sample + slot) * CHUNKT) * D);

    const int base = blockIdx.z * 4096;      // 8 slabs x 4096 float4 = 32768
    #pragma unroll 4
    for (int i = base + threadIdx.x; i < base + 4096; i += 256) {
        float4 v = src[i];
        dst[i] = make_uint2(f2h2(v.x, v.y), f2h2(v.z, v.w));
    }
}

// ---------------------------------------------------------------------------
// Kernel 3: fp16 mma.sync GEMM (f32 accum). One CTA = 128(M)x128(N), K = D.
// A and B fp16 in smem, cp.async 3-stage pipeline. All fragments loaded via
// ldmatrix.x4 (6 LDSM per warp-k16 vs 24 LDS.32). 8 warps (2m x 4n).
// Epilogue fuses (+bias +PE(t,h)) * sqrt(128). Dead slots zero-fill.
// ---------------------------------------------------------------------------
__global__ void __launch_bounds__(256, 2)
chunk_gemm_mma(const float* __restrict__ bias,
               const int* __restrict__ chunk_idx,
               float* __restrict__ out,
               int D, int H, int sample) {
    extern __shared__ __align__(16) char smem[];
    __shared__ float s_div[BN / 2];
    __shared__ float s_bias[BN];

    const int ntile = blockIdx.x;
    const int slot  = blockIdx.y;
    const int b     = blockIdx.z;
    const int n0    = ntile * BN;
    const int Smax  = sample * CHUNKT;
    const int tid   = threadIdx.x;
    const int wid   = tid >> 5;
    const int lane  = tid & 31;

    float* outp = out + ((size_t)b * Smax + (size_t)slot * CHUNKT) * H + n0;

    const unsigned long long m = sel_mask(chunk_idx, b, sample);
    const int nsel = __popcll(m);

    if (slot >= nsel) {                      // zero-fill 128 x 128 tile
        float4 z = make_float4(0.f, 0.f, 0.f, 0.f);
        #pragma unroll
        for (int i = 0; i < 16; ++i) {
            int idx = i * 256 + tid;
            int r = idx >> 5, c4 = (idx & 31) * 4;
            *reinterpret_cast<float4*>(outp + (size_t)r * H + c4) = z;
        }
        return;
    }
    const int chunk = nth_set_bit(m, slot);  // PE time index

    const __half* Agm = g_A16 + ((size_t)(b * sample + slot) * CHUNKT) * D;
    const __half* Bgm = g_WT + (size_t)n0 * D;

    if (tid < BN / 2)
        s_div[tid] = __expf((float)(2 * ((n0 >> 1) + tid)) * (-9.210340371976184f / (float)H));
    if (tid < BN) s_bias[tid] = bias[n0 + tid];

    const uint32_t sbase = cvta_shared(smem);

    // cp.async: per stage each matrix = 128 rows x 32 halves (4 x 16B/row),
    // 512 copies per matrix, 2 per thread.
    auto load_stage = [&](int kc, int st) {
        const int k0 = kc * BK;
        const uint32_t abase = sbase + st * STAGEB;
        const uint32_t bbase = abase + AMATB;
        #pragma unroll
        for (int i = 0; i < 2; ++i) {
            int idx = i * 256 + tid;
            int r = idx >> 2, kp = idx & 3;
            cp_async16(abase + r * (KSTR * 2) + kp * 16,
                       Agm + (size_t)r * D + k0 + kp * 8);
        }
        #pragma unroll
        for (int i = 0; i < 2; ++i) {
            int idx = i * 256 + tid;
            int r = idx >> 2, kp = idx & 3;
            cp_async16(bbase + r * (KSTR * 2) + kp * 16,
                       Bgm + (size_t)r * D + k0 + kp * 8);
        }
        asm volatile("cp.async.commit_group;" ::: "memory");
    };

    // Warp tiling: wm in {0,1} (64 rows), wn in {0..3} (32 cols)
    const int wm = wid & 1;
    const int wn = wid >> 1;

    // ldmatrix per-lane offsets (bytes, stage-relative).
    // group = lane>>3, gr = lane&7.
    // A x4 (per mt): g0 = (m lo, k lo), g1 = (m hi, k lo), g2 = (m lo, k hi),
    //                g3 = (m hi, k hi)  -> regs {af0, af1, af2, af3}
    // B x4 (per nt-pair): g0 = (n lo, k lo), g1 = (n lo, k hi),
    //                     g2 = (n hi, k lo), g3 = (n hi, k hi)
    //                -> regs {bf[2p][0], bf[2p][1], bf[2p+1][0], bf[2p+1][1]}
    const int grp = lane >> 3, gr = lane & 7;
    uint32_t offA[4], offB[2];
    #pragma unroll
    for (int mt = 0; mt < 4; ++mt) {
        int row = wm * 64 + mt * 16 + (grp & 1) * 8 + gr;
        offA[mt] = (uint32_t)((row * KSTR + (grp >> 1) * 8) * 2);
    }
    #pragma unroll
    for (int p = 0; p < 2; ++p) {
        int row = wn * 32 + p * 16 + (grp >> 1) * 8 + gr;
        offB[p] = (uint32_t)(AMATB + (row * KSTR + (grp & 1) * 8) * 2);
    }

    float acc[4][4][4];
    #pragma unroll
    for (int mt = 0; mt < 4; ++mt)
        #pragma unroll
        for (int nt = 0; nt < 4; ++nt)
            #pragma unroll
            for (int q = 0; q < 4; ++q) acc[mt][nt][q] = 0.f;

    const int NCH = D / BK;                  // 32
    load_stage(0, 0);
    load_stage(1, 1);

    for (int c = 0; c < NCH; ++c) {
        asm volatile("cp.async.wait_group 1;" ::: "memory");
        __syncthreads();
        if (c + 2 < NCH) load_stage(c + 2, (c + 2) % NSTAGE);
        else             asm volatile("cp.async.commit_group;" ::: "memory");

        const uint32_t stg = sbase + (c % NSTAGE) * STAGEB;

        #pragma unroll
        for (int k16 = 0; k16 < 2; ++k16) {
            const uint32_t kadd = k16 * 32;  // 16 halves
            uint32_t af[4][4], bf[4][2];
            #pragma unroll
            for (int mt = 0; mt < 4; ++mt)
                ldsm4(af[mt][0], af[mt][1], af[mt][2], af[mt][3],
                      stg + offA[mt] + kadd);
            ldsm4(bf[0][0], bf[0][1], bf[1][0], bf[1][1], stg + offB[0] + kadd);
            ldsm4(bf[2][0], bf[2][1], bf[3][0], bf[3][1], stg + offB[1] + kadd);
            #pragma unroll
            for (int mt = 0; mt < 4; ++mt)
                #pragma unroll
                for (int nt = 0; nt < 4; ++nt)
                    mma_f16(acc[mt][nt], af[mt][0], af[mt][1], af[mt][2], af[mt][3],
                            bf[nt][0], bf[nt][1]);
        }
    }

    // Epilogue: (acc + bias + PE(t,h)) * sqrt(128)
    const float scale = 11.313708498984761f;   // sqrt(128)
    const int   qrow  = lane >> 2;             // 0..7
    const int   qcol  = (lane & 3) * 2;        // 0,2,4,6

    #pragma unroll
    for (int mt = 0; mt < 4; ++mt) {
        #pragma unroll
        for (int nt = 0; nt < 4; ++nt) {
            const int col = wn * 32 + nt * 8 + qcol;     // even local col
            const float bs0 = s_bias[col], bs1 = s_bias[col + 1];
            const float dv  = s_div[col >> 1];
            #pragma unroll
            for (int h = 0; h < 2; ++h) {                // row halves (+0, +8)
                const int row = wm * 64 + mt * 16 + h * 8 + qrow;
                float s, cc;
                __sincosf((float)(chunk * CHUNKT + row) * dv, &s, &cc);
                float2 v;
                v.x = (acc[mt][nt][h * 2 + 0] + bs0 + s)  * scale;
                v.y = (acc[mt][nt][h * 2 + 1] + bs1 + cc) * scale;
                *reinterpret_cast<float2*>(outp + (size_t)row * H + col) = v;
            }
        }
    }
}

// ---------------------------------------------------------------------------
// Launcher. Inputs: state, data, W, b, chunk_idx. Output float32.
// ---------------------------------------------------------------------------
extern "C" void kernel_launch(void* const* d_in, const int* in_sizes, int n_in,
                              void* d_out, int out_size) {
    const float* data      = (const float*)d_in[1];
    const float* W         = (const float*)d_in[2];
    const float* bias      = (const float*)d_in[3];
    const int*   chunk_idx = (const int*)d_in[4];
    float*       out       = (float*)d_out;

    const int H = in_sizes[3];                // 1024
    const int D = in_sizes[2] / H;            // 1024
    const int B = in_sizes[0] / (64 * H);     // 8
    const int T = in_sizes[1] / (B * D);      // 8192
    const int sample = in_sizes[4] / B;       // 16

    transpose_kernel<<<dim3(H / 32, D / 32), dim3(32, 8)>>>(W, D, H);
    convert_a_kernel<<<dim3(sample, B, 8), 256>>>(data, chunk_idx, D, T, sample);

    const int SMEM_BYTES = NSTAGE * STAGEB;   // 61440
    cudaFuncSetAttribute(chunk_gemm_mma,
                         cudaFuncAttributeMaxDynamicSharedMemorySize, SMEM_BYTES);
    dim3 grid(H / BN, sample, B);
    chunk_gemm_mma<<<grid, 256, SMEM_BYTES>>>(bias, chunk_idx, out, D, H, sample);
}